// round 2
// baseline (speedup 1.0000x reference)
#include <cuda_runtime.h>
#include <cuda_bf16.h>
#include <cstdint>

// upfirdn2d(x, outer([1,3,3,1])*4/64, up=2, pad=(2,1))
// Per-dim reduction: even out 2i = .75*x[i] + .25*x[i-1]
//                    odd  out 2i+1 = .75*x[i] + .25*x[i+1]
// One warp per output row. Lane l loads input cols {2l, 2l+1} (float2) from
// rows iy and iy_neighbor; cols 2l-1 / 2l+2 come via warp shuffle.
// Writes one float4 (output cols 4l..4l+3) per lane.

static constexpr int H  = 64;
static constexpr int W  = 64;
static constexpr int OH = 128;
static constexpr int OW = 128;

__global__ __launch_bounds__(256) void upsample_fir_kernel(
    const float* __restrict__ x, float* __restrict__ out, int n_rows_total)
{
    const int gw   = (blockIdx.x * blockDim.x + threadIdx.x) >> 5;  // global warp = output row id
    const int lane = threadIdx.x & 31;
    if (gw >= n_rows_total) return;

    const int plane = gw >> 7;       // / OH
    const int oy    = gw & (OH - 1); // % OH

    const float* __restrict__ xp = x   + (size_t)plane * (H * W);
    float*       __restrict__ op = out + (size_t)plane * (OH * OW);

    const int iy  = oy >> 1;
    const int iyn = (oy & 1) ? (iy + 1) : (iy - 1);   // 0.25-weight row

    // Row iy is always in range.
    float2 a = *reinterpret_cast<const float2*>(xp + iy * W + 2 * lane);
    float2 b = make_float2(0.f, 0.f);
    if ((unsigned)iyn < (unsigned)H)
        b = *reinterpret_cast<const float2*>(xp + iyn * W + 2 * lane);

    // Horizontal neighbors across lanes (zero at tile edges = zero padding).
    float a_prev = __shfl_up_sync(0xffffffffu, a.y, 1);
    float b_prev = __shfl_up_sync(0xffffffffu, b.y, 1);
    float a_next = __shfl_down_sync(0xffffffffu, a.x, 1);
    float b_next = __shfl_down_sync(0xffffffffu, b.x, 1);
    if (lane == 0)  { a_prev = 0.f; b_prev = 0.f; }
    if (lane == 31) { a_next = 0.f; b_next = 0.f; }

    const float W0 = 0.75f, W1 = 0.25f;

    // Horizontal filtering per row (output cols 4l .. 4l+3)
    float ha0 = W0 * a.x + W1 * a_prev;   // ox=4l   (even, ix=2l)
    float ha1 = W0 * a.x + W1 * a.y;      // ox=4l+1 (odd,  ix=2l)
    float ha2 = W0 * a.y + W1 * a.x;      // ox=4l+2 (even, ix=2l+1)
    float ha3 = W0 * a.y + W1 * a_next;   // ox=4l+3 (odd,  ix=2l+1)

    float hb0 = W0 * b.x + W1 * b_prev;
    float hb1 = W0 * b.x + W1 * b.y;
    float hb2 = W0 * b.y + W1 * b.x;
    float hb3 = W0 * b.y + W1 * b_next;

    // Vertical blend: 0.75 * row(iy) + 0.25 * row(iyn)
    float4 o;
    o.x = W0 * ha0 + W1 * hb0;
    o.y = W0 * ha1 + W1 * hb1;
    o.z = W0 * ha2 + W1 * hb2;
    o.w = W0 * ha3 + W1 * hb3;

    *reinterpret_cast<float4*>(op + oy * OW + 4 * lane) = o;
}

extern "C" void kernel_launch(void* const* d_in, const int* in_sizes, int n_in,
                              void* d_out, int out_size)
{
    const float* x = (const float*)d_in[0];
    float* out = (float*)d_out;

    // 16 * 256 planes, 128 output rows each; one warp per row.
    const int n_rows_total = (16 * 256) * OH;           // 524288
    const int threads = 256;                            // 8 warps/block
    const int blocks  = n_rows_total / (threads / 32);  // 65536

    upsample_fir_kernel<<<blocks, threads>>>(x, out, n_rows_total);
}

// round 3
// speedup vs baseline: 1.2884x; 1.2884x over previous
#include <cuda_runtime.h>
#include <cuda_bf16.h>
#include <cstdint>

// upfirdn2d(x, outer([1,3,3,1])*4/64, up=2, pad=(2,1))
// Per-dim reduction: even out 2i  = .75*x[i] + .25*x[i-1]
//                    odd  out 2i+1 = .75*x[i] + .25*x[i+1]
//
// One warp per OUTPUT ROW PAIR (2i, 2i+1). The pair shares input row i:
// load rows i-1, i, i+1 once, horizontal-filter each once, emit both
// output rows (2 x 512B coalesced stores per warp).

static constexpr int H  = 64;
static constexpr int W  = 64;
static constexpr int OW = 128;

__global__ __launch_bounds__(256) void upsample_fir_pair_kernel(
    const float* __restrict__ x, float* __restrict__ out)
{
    const int gw   = (blockIdx.x << 3) + (threadIdx.x >> 5); // global warp = row-pair id
    const int lane = threadIdx.x & 31;

    const int plane = gw >> 6;        // / H  (64 pairs per plane)
    const int i     = gw & (H - 1);   // center input row

    const float* __restrict__ xp = x   + plane * (H * W) + 2 * lane;
    float*       __restrict__ op = out + plane * (2 * H * OW) + (i << 8) + 4 * lane;

    // Load 3 input rows (float2 = input cols 2l, 2l+1). Edge rows -> zero pad.
    float2 c = *reinterpret_cast<const float2*>(xp + i * W);
    float2 p = make_float2(0.f, 0.f);
    float2 n = make_float2(0.f, 0.f);
    if (i > 0)     p = *reinterpret_cast<const float2*>(xp + (i - 1) * W);
    if (i < H - 1) n = *reinterpret_cast<const float2*>(xp + (i + 1) * W);

    // Cross-lane horizontal neighbors (zero at row edges = zero padding).
    float c_prev = __shfl_up_sync(0xffffffffu, c.y, 1);
    float p_prev = __shfl_up_sync(0xffffffffu, p.y, 1);
    float n_prev = __shfl_up_sync(0xffffffffu, n.y, 1);
    float c_next = __shfl_down_sync(0xffffffffu, c.x, 1);
    float p_next = __shfl_down_sync(0xffffffffu, p.x, 1);
    float n_next = __shfl_down_sync(0xffffffffu, n.x, 1);
    if (lane == 0)  { c_prev = 0.f; p_prev = 0.f; n_prev = 0.f; }
    if (lane == 31) { c_next = 0.f; p_next = 0.f; n_next = 0.f; }

    const float W0 = 0.75f, W1 = 0.25f;

    // Horizontal filter each input row once -> 4 output columns per lane.
    float hc0 = W0 * c.x + W1 * c_prev;
    float hc1 = W0 * c.x + W1 * c.y;
    float hc2 = W0 * c.y + W1 * c.x;
    float hc3 = W0 * c.y + W1 * c_next;

    float hp0 = W0 * p.x + W1 * p_prev;
    float hp1 = W0 * p.x + W1 * p.y;
    float hp2 = W0 * p.y + W1 * p.x;
    float hp3 = W0 * p.y + W1 * p_next;

    float hn0 = W0 * n.x + W1 * n_prev;
    float hn1 = W0 * n.x + W1 * n.y;
    float hn2 = W0 * n.y + W1 * n.x;
    float hn3 = W0 * n.y + W1 * n_next;

    // Vertical blend: out row 2i = .75*hc + .25*hp ; out row 2i+1 = .75*hc + .25*hn
    float4 e, o;
    e.x = W0 * hc0 + W1 * hp0;
    e.y = W0 * hc1 + W1 * hp1;
    e.z = W0 * hc2 + W1 * hp2;
    e.w = W0 * hc3 + W1 * hp3;

    o.x = W0 * hc0 + W1 * hn0;
    o.y = W0 * hc1 + W1 * hn1;
    o.z = W0 * hc2 + W1 * hn2;
    o.w = W0 * hc3 + W1 * hn3;

    *reinterpret_cast<float4*>(op)      = e;
    *reinterpret_cast<float4*>(op + OW) = o;
}

extern "C" void kernel_launch(void* const* d_in, const int* in_sizes, int n_in,
                              void* d_out, int out_size)
{
    const float* x = (const float*)d_in[0];
    float* out = (float*)d_out;

    // 16 * 256 planes, 64 row-pairs each; one warp per pair.
    const int n_pairs = 16 * 256 * H;               // 262144
    const int threads = 256;                        // 8 warps/block
    const int blocks  = n_pairs / (threads / 32);   // 32768

    upsample_fir_pair_kernel<<<blocks, threads>>>(x, out);
}